// round 13
// baseline (speedup 1.0000x reference)
#include <cuda_runtime.h>
#include <cuda_fp16.h>
#include <cstdint>

#define DEV_INLINE __device__ __forceinline__

// ---------------- scratch (device globals; allocation-free) ----------------
__device__ __align__(16) __half g_vt[256u * 4096u];   // V fp16
__device__ __align__(16) __half g_ut[4096u * 256u];   // U fp16

// ---------------- PTX helpers ----------------
DEV_INLINE uint32_t smem_u32(const void* p) {
    uint32_t a;
    asm("{ .reg .u64 t; cvta.to.shared.u64 t, %1; cvt.u32.u64 %0, t; }"
        : "=r"(a) : "l"(p));
    return a;
}

#define CP_ASYNC16(dst, src) \
    asm volatile("cp.async.cg.shared.global [%0], [%1], 16;" :: "r"(dst), "l"(src))
#define CP_COMMIT() asm volatile("cp.async.commit_group;" ::: "memory")
#define CP_WAIT1()  asm volatile("cp.async.wait_group 1;" ::: "memory")
#define CP_WAIT2()  asm volatile("cp.async.wait_group 2;" ::: "memory")

#define LDSM4(r, addr) \
    asm volatile("ldmatrix.sync.aligned.m8n8.x4.shared.b16 {%0,%1,%2,%3}, [%4];" \
                 : "=r"((r)[0]), "=r"((r)[1]), "=r"((r)[2]), "=r"((r)[3]) \
                 : "r"(addr))

#define MMA_F16(d, a, b) \
    asm volatile("mma.sync.aligned.m16n8k16.row.col.f32.f16.f16.f32 " \
                 "{%0,%1,%2,%3},{%4,%5,%6,%7},{%8,%9},{%0,%1,%2,%3};" \
                 : "+f"((d)[0]), "+f"((d)[1]), "+f"((d)[2]), "+f"((d)[3]) \
                 : "r"((a)[0]), "r"((a)[1]), "r"((a)[2]), "r"((a)[3]), \
                   "r"((b)[0]), "r"((b)[1]))

// ---------------- geometry ----------------
// phase 1: BM=64, BN=256 (full rank), KT=32, stride 40 halves (80B = 5x16B, odd: conflict-free)
static constexpr int STR1 = 40;
static constexpr int NST1 = 4;
static constexpr uint32_t A1_B    = 64u  * STR1 * 2u;   // 5120
static constexpr uint32_t B1_B    = 256u * STR1 * 2u;   // 20480
static constexpr uint32_t STG1_B  = A1_B + B1_B;        // 25600
// T in smem: 64 x 264 halves (256 data + 8 pad; 528B = 33x16B, odd: conflict-free)
static constexpr int STRT = 264;
static constexpr uint32_t T_B = 64u * STRT * 2u;        // 33792
// phase 2: U half-chunks 128 rows x 128 k-halves, stride 136 (272B = 17x16B, odd)
static constexpr int STRU = 136;
static constexpr int NSTU = 3;
static constexpr uint32_t UCH_B = 128u * STRU * 2u;     // 34816
static constexpr uint32_t P1OFF = T_B;                  // phase-1 pipe / U ring both live here
static constexpr uint32_t SMEM_SZ = P1OFF + NST1 * STG1_B > P1OFF + NSTU * UCH_B
                                  ? P1OFF + NST1 * STG1_B : P1OFF + NSTU * UCH_B;  // 138240

// ---------------- convert V and U to fp16 ----------------
__global__ void cvt_vu(const float* __restrict__ V, __half* __restrict__ vt,
                       const float* __restrict__ U, __half* __restrict__ ut, int n1) {
    int i = (blockIdx.x * 256 + threadIdx.x) * 4;
    const float* s; __half* d;
    if (i < n1) { s = V; d = vt; }
    else        { s = U; d = ut; i -= n1; }
    float4 v = *reinterpret_cast<const float4*>(&s[i]);
    __half2 p0 = __floats2half2_rn(v.x, v.y);
    __half2 p1 = __floats2half2_rn(v.z, v.w);
    *reinterpret_cast<__half2*>(&d[i])     = p0;
    *reinterpret_cast<__half2*>(&d[i + 2]) = p1;
}

// ---------------- fused kernel: out_band = (x_band @ V^T) @ U^T + bias ----------------
// grid = 128 m-bands of 64 rows; 256 threads; occ 1.
__global__ __launch_bounds__(256, 1)
void lr_fused(const float* __restrict__ X, const __half* __restrict__ Vt,
              const __half* __restrict__ Ut, const float* __restrict__ bias,
              float* __restrict__ Out) {
    extern __shared__ __align__(16) char smem[];
    const uint32_t sb = smem_u32(smem);

    const int tid  = threadIdx.x;
    const int lane = tid & 31;
    const int warp = tid >> 5;
    const int wm = warp & 1, wn = warp >> 1;      // 2 x 4 warp grid
    const int m0 = blockIdx.x * 64;

    const int lr = lane & 7, lm = lane >> 3;
    const int er = lane >> 2, ec = (lane & 3) * 2;

    // ================= phase 1: T[64,256] = x_band[64,4096] @ V^T =================
    const int nk1 = 4096 / 32;                    // 128 iterations

    // A producer: x fp32 -> fp16 in-reg -> STS. row apr (0..63), k off apk*1f (8 floats)
    const int apr = tid >> 2, apk = (tid & 3) * 8;
    const float* Xb = X + (size_t)(m0 + apr) * 4096 + apk;
    const uint32_t adst = (uint32_t)(apr * STR1 + apk) * 2;
    // B producer: V row bpr (0..255), 4x16B
    const int bpr = tid;
    const __half* Vb = Vt + (size_t)bpr * 4096;
    const uint32_t bdst = (uint32_t)bpr * STR1 * 2;

    auto produceB = [&](int j) {
        if (j < nk1) {
            const uint32_t st = sb + P1OFF + (uint32_t)(j % NST1) * STG1_B + A1_B;
            const __half* src = Vb + (size_t)j * 32;
            CP_ASYNC16(st + bdst,      src);
            CP_ASYNC16(st + bdst + 16, src + 8);
            CP_ASYNC16(st + bdst + 32, src + 16);
            CP_ASYNC16(st + bdst + 48, src + 24);
        }
        CP_COMMIT();
    };

    float ra[8];
    auto loadA = [&](int j) {
        if (j < nk1) {
            const float* p = Xb + (size_t)j * 32;
            float4 v0 = *reinterpret_cast<const float4*>(p);
            float4 v1 = *reinterpret_cast<const float4*>(p + 4);
            ra[0] = v0.x; ra[1] = v0.y; ra[2] = v0.z; ra[3] = v0.w;
            ra[4] = v1.x; ra[5] = v1.y; ra[6] = v1.z; ra[7] = v1.w;
        }
    };
    auto stsA = [&](int j) {
        const uint32_t st = P1OFF + (uint32_t)(j % NST1) * STG1_B;
        __half2 p0 = __floats2half2_rn(ra[0], ra[1]);
        __half2 p1 = __floats2half2_rn(ra[2], ra[3]);
        __half2 p2 = __floats2half2_rn(ra[4], ra[5]);
        __half2 p3 = __floats2half2_rn(ra[6], ra[7]);
        uint4 v;
        v.x = *reinterpret_cast<uint32_t*>(&p0);
        v.y = *reinterpret_cast<uint32_t*>(&p1);
        v.z = *reinterpret_cast<uint32_t*>(&p2);
        v.w = *reinterpret_cast<uint32_t*>(&p3);
        *reinterpret_cast<uint4*>(smem + st + adst) = v;
    };

    float acc1[2][8][4];
#pragma unroll
    for (int mt = 0; mt < 2; mt++)
#pragma unroll
        for (int nt = 0; nt < 8; nt++)
#pragma unroll
            for (int e = 0; e < 4; e++) acc1[mt][nt][e] = 0.0f;

    const uint32_t offA1 = (uint32_t)(((lm & 1) * 8 + lr) * STR1 + (lm >> 1) * 8) * 2;
    const uint32_t offB1 = (uint32_t)(((lm >> 1) * 8 + lr) * STR1 + (lm & 1) * 8) * 2;
    const uint32_t rowA1 = (uint32_t)(wm * 32) * STR1 * 2;
    const uint32_t rowB1 = (uint32_t)(wn * 64) * STR1 * 2;

    loadA(0);
    produceB(0);
    produceB(1);
    produceB(2);

    for (int i = 0; i < nk1; i++) {
        stsA(i);
        loadA(i + 1);
        CP_WAIT2();
        __syncthreads();
        produceB(i + 3);
        const uint32_t st = sb + P1OFF + (uint32_t)(i % NST1) * STG1_B;
        const uint32_t aB = st + rowA1 + offA1;
        const uint32_t bB = st + A1_B + rowB1 + offB1;
#pragma unroll
        for (int ks = 0; ks < 2; ks++) {
            const uint32_t kb = (uint32_t)ks * 16 * 2;
            uint32_t a[2][4], b[16];
            LDSM4(a[0], aB + kb);
            LDSM4(a[1], aB + kb + 16u * STR1 * 2);
#pragma unroll
            for (int p = 0; p < 4; p++)
                LDSM4(&b[p * 4], bB + kb + (uint32_t)p * 16u * STR1 * 2);
#pragma unroll
            for (int mt = 0; mt < 2; mt++)
#pragma unroll
                for (int nt = 0; nt < 8; nt++)
                    MMA_F16(acc1[mt][nt], a[mt], (&b[nt * 2]));
        }
    }

    __syncthreads();   // all phase-1 consumption done; pipe region reusable

    // ================= transition: prefetch U, write T to smem =================
    // U producer mapping: row upr (0..127), half uh (0/1) of the 256B k-row
    const int upr = tid >> 1, uh = tid & 1;
    const uint32_t udst = (uint32_t)upr * STRU * 2 + (uint32_t)uh * 128;

    auto produceU = [&](int j) {
        if (j < 64) {
            const int nb = j >> 1, kh = j & 1;
            const uint32_t st = sb + P1OFF + (uint32_t)(j % NSTU) * UCH_B;
            const __half* src = Ut + (size_t)(nb * 128 + upr) * 256 + kh * 128 + uh * 64;
#pragma unroll
            for (int q = 0; q < 8; q++)
                CP_ASYNC16(st + udst + (uint32_t)q * 16, src + q * 8);
        }
        CP_COMMIT();
    };

    produceU(0);
    produceU(1);

    // write T (fp16, rn) into smem region [0, T_B)
#pragma unroll
    for (int nt = 0; nt < 8; nt++) {
        const int col = wn * 64 + nt * 8 + ec;
#pragma unroll
        for (int mt = 0; mt < 2; mt++) {
            const int row = wm * 32 + mt * 16 + er;
            __half2 t0 = __floats2half2_rn(acc1[mt][nt][0], acc1[mt][nt][1]);
            __half2 t1 = __floats2half2_rn(acc1[mt][nt][2], acc1[mt][nt][3]);
            *reinterpret_cast<__half2*>(smem + ((size_t)row * STRT + col) * 2)       = t0;
            *reinterpret_cast<__half2*>(smem + ((size_t)(row + 8) * STRT + col) * 2) = t1;
        }
    }
    __syncthreads();   // T visible to all warps

    // ================= phase 2: out_band = T @ U^T + bias =================
    const uint32_t offAT = (uint32_t)(((lm & 1) * 8 + lr) * STRT + (lm >> 1) * 8) * 2;
    const uint32_t offBU = (uint32_t)(((lm >> 1) * 8 + lr) * STRU + (lm & 1) * 8) * 2;
    const uint32_t rowBU = (uint32_t)(wn * 32) * STRU * 2;

    float acc2[2][4][4];
#pragma unroll
    for (int mt = 0; mt < 2; mt++)
#pragma unroll
        for (int nt = 0; nt < 4; nt++)
#pragma unroll
            for (int e = 0; e < 4; e++) acc2[mt][nt][e] = 0.0f;

    for (int j = 0; j < 64; j++) {
        CP_WAIT1();
        __syncthreads();
        produceU(j + 2);
        const int nb = j >> 1, kh = j & 1;
        const uint32_t ub = sb + P1OFF + (uint32_t)(j % NSTU) * UCH_B;
#pragma unroll
        for (int kk = 0; kk < 8; kk++) {
            const uint32_t kcol2 = (uint32_t)(kh * 128 + kk * 16) * 2;
            uint32_t a[2][4], b[8];
#pragma unroll
            for (int mt = 0; mt < 2; mt++)
                LDSM4(a[mt], sb + (uint32_t)(wm * 32 + mt * 16) * STRT * 2 + kcol2 + offAT);
            LDSM4(&b[0], ub + rowBU + (uint32_t)kk * 16 * 2 + offBU);
            LDSM4(&b[4], ub + rowBU + 16u * STRU * 2 + (uint32_t)kk * 16 * 2 + offBU);
#pragma unroll
            for (int mt = 0; mt < 2; mt++)
#pragma unroll
                for (int nt = 0; nt < 4; nt++)
                    MMA_F16(acc2[mt][nt], a[mt], (&b[nt * 2]));
        }
        if (j & 1) {
            // epilogue for n-chunk nb
#pragma unroll
            for (int nt = 0; nt < 4; nt++) {
                const int col = nb * 128 + wn * 32 + nt * 8 + ec;
                const float b0 = bias[col], b1 = bias[col + 1];
#pragma unroll
                for (int mt = 0; mt < 2; mt++) {
                    const int row = m0 + wm * 32 + mt * 16 + er;
                    float2 o0 = make_float2(acc2[mt][nt][0] + b0, acc2[mt][nt][1] + b1);
                    float2 o1 = make_float2(acc2[mt][nt][2] + b0, acc2[mt][nt][3] + b1);
                    *reinterpret_cast<float2*>(&Out[(size_t)row * 4096 + col])       = o0;
                    *reinterpret_cast<float2*>(&Out[(size_t)(row + 8) * 4096 + col]) = o1;
                }
            }
#pragma unroll
            for (int mt = 0; mt < 2; mt++)
#pragma unroll
                for (int nt = 0; nt < 4; nt++)
#pragma unroll
                    for (int e = 0; e < 4; e++) acc2[mt][nt][e] = 0.0f;
        }
    }
}

// ---------------- launch ----------------
extern "C" void kernel_launch(void* const* d_in, const int* in_sizes, int n_in,
                              void* d_out, int out_size) {
    const float* x    = (const float*)d_in[0];   // [8192, 4096]
    const float* U    = (const float*)d_in[1];   // [4096, 256]
    const float* V    = (const float*)d_in[2];   // [256, 4096]
    const float* bias = (const float*)d_in[3];   // [4096]
    float* out = (float*)d_out;                  // [8192, 4096]

    __half *vt, *ut;
    cudaGetSymbolAddress((void**)&vt, g_vt);
    cudaGetSymbolAddress((void**)&ut, g_ut);

    cudaFuncSetAttribute(lr_fused, cudaFuncAttributeMaxDynamicSharedMemorySize, SMEM_SZ);

    // convert V and U to fp16 (one tiny launch)
    const int n1 = 256 * 4096;
    cvt_vu<<<(2 * n1 / 4) / 256, 256>>>(V, vt, U, ut, n1);

    // fused low-rank linear: 128 m-band CTAs
    lr_fused<<<128, 256, SMEM_SZ>>>(x, vt, ut, bias, out);
}

// round 14
// speedup vs baseline: 1.3778x; 1.3778x over previous
#include <cuda_runtime.h>
#include <cuda_fp16.h>
#include <cstdint>

#define DEV_INLINE __device__ __forceinline__

// ---------------- scratch (device globals; allocation-free) ----------------
__device__ __align__(16) __half g_vt[256u * 4096u];   // V fp16
__device__ __align__(16) __half g_ut[4096u * 256u];   // U fp16
__device__ __align__(16) __half g_t [8192u * 256u];   // T fp16

// ---------------- PTX helpers ----------------
DEV_INLINE uint32_t smem_u32(const void* p) {
    uint32_t a;
    asm("{ .reg .u64 t; cvta.to.shared.u64 t, %1; cvt.u32.u64 %0, t; }"
        : "=r"(a) : "l"(p));
    return a;
}

#define CP_ASYNC16(dst, src) \
    asm volatile("cp.async.cg.shared.global [%0], [%1], 16;" :: "r"(dst), "l"(src))
#define CP_COMMIT() asm volatile("cp.async.commit_group;" ::: "memory")
#define CP_WAIT1()  asm volatile("cp.async.wait_group 1;" ::: "memory")
#define CP_WAIT2()  asm volatile("cp.async.wait_group 2;" ::: "memory")

#define LDSM4(r, addr) \
    asm volatile("ldmatrix.sync.aligned.m8n8.x4.shared.b16 {%0,%1,%2,%3}, [%4];" \
                 : "=r"((r)[0]), "=r"((r)[1]), "=r"((r)[2]), "=r"((r)[3]) \
                 : "r"(addr))

#define MMA_F16(d, a, b) \
    asm volatile("mma.sync.aligned.m16n8k16.row.col.f32.f16.f16.f32 " \
                 "{%0,%1,%2,%3},{%4,%5,%6,%7},{%8,%9},{%0,%1,%2,%3};" \
                 : "+f"((d)[0]), "+f"((d)[1]), "+f"((d)[2]), "+f"((d)[3]) \
                 : "r"((a)[0]), "r"((a)[1]), "r"((a)[2]), "r"((a)[3]), \
                   "r"((b)[0]), "r"((b)[1]))

// ---------------- tiling constants ----------------
static constexpr int KT = 32;                          // halves per K-chunk
static constexpr int STRIDE = 40;                      // halves per smem row (pad)
// stage 1: BM=64, BN=128, NST=4
static constexpr int NST1 = 4;
static constexpr uint32_t A1_TILE_B = 64u  * STRIDE * 2u;  // 5120 B
static constexpr uint32_t B1_TILE_B = 128u * STRIDE * 2u;  // 10240 B
static constexpr uint32_t STAGE1_B  = A1_TILE_B + B1_TILE_B;  // 15360 B
static constexpr uint32_t SMEM1_SZ  = NST1 * STAGE1_B;        // 61440 B (occ 2)
// stage 2: BM=128, BN=128, NST=4
static constexpr int NST2 = 4;
static constexpr uint32_t A2_TILE_B = 128u * STRIDE * 2u;  // 10240 B
static constexpr uint32_t STAGE2_B  = 2u * A2_TILE_B;      // 20480 B
static constexpr uint32_t SMEM2_SZ  = NST2 * STAGE2_B;     // 81920 B (occ 2)

// ---------------- convert V and U to fp16 ----------------
__global__ void cvt_vu(const float* __restrict__ V, __half* __restrict__ vt,
                       const float* __restrict__ U, __half* __restrict__ ut, int n1) {
    int i = (blockIdx.x * 256 + threadIdx.x) * 4;
    const float* s; __half* d;
    if (i < n1) { s = V; d = vt; }
    else        { s = U; d = ut; i -= n1; }
    float4 v = *reinterpret_cast<const float4*>(&s[i]);
    __half2 p0 = __floats2half2_rn(v.x, v.y);
    __half2 p1 = __floats2half2_rn(v.z, v.w);
    *reinterpret_cast<__half2*>(&d[i])     = p0;
    *reinterpret_cast<__half2*>(&d[i + 2]) = p1;
}

// ---------------- Stage 1: T = x @ V^T ----------------
// x fp32 LDG -> cvt fp16 in-reg -> STS; V pre-converted.
// BM=64, BN=128, 256 thr, warp 2x4 (tile 32x32), NST=4, occ 2.
// Inner loop: ALL fragment LDSM hoisted ahead of the MMA burst.
__global__ __launch_bounds__(256, 2)
void lr_gemm_s1(const float* __restrict__ X, const __half* __restrict__ Vt,
                int K, __half* __restrict__ T) {
    extern __shared__ __align__(16) char smem[];
    const uint32_t sb = smem_u32(smem);

    const int tid  = threadIdx.x;
    const int lane = tid & 31;
    const int warp = tid >> 5;
    const int wm = warp & 1, wn = warp >> 1;
    const int m0 = blockIdx.y * 64;
    const int n0 = blockIdx.x * 128;
    const int nk = K / KT;   // 128

    // A producer: row = tid>>2 (0..63), k-offset (tid&3)*8 elems (16B of fp16)
    const int apr = tid >> 2, apk = (tid & 3) * 8;
    // B producer: row = tid>>1 (0..127), byte offset (tid&1)*32; 2x16B per thread
    const int bpr = tid >> 1, bpb = (tid & 1) * 32;

    const float*  Xb  = X  + (size_t)(m0 + apr) * K + apk;
    const __half* Vb  = Vt + (size_t)(n0 + bpr) * K;
    const uint32_t adst = (uint32_t)(apr * STRIDE + apk) * 2;   // bytes
    const uint32_t bdst = (uint32_t)(bpr * STRIDE) * 2 + bpb;   // bytes

    auto produceB = [&](int j) {
        if (j < nk) {
            const uint32_t st = sb + (uint32_t)(j % NST1) * STAGE1_B + A1_TILE_B;
            const __half* src = Vb + (size_t)j * KT + bpb / 2;
            CP_ASYNC16(st + bdst,      src);
            CP_ASYNC16(st + bdst + 16, src + 8);
        }
        CP_COMMIT();
    };

    float ra[8];
    auto loadA = [&](int j) {
        if (j < nk) {
            const float* p = Xb + (size_t)j * KT;
            float4 v0 = *reinterpret_cast<const float4*>(p);
            float4 v1 = *reinterpret_cast<const float4*>(p + 4);
            ra[0] = v0.x; ra[1] = v0.y; ra[2] = v0.z; ra[3] = v0.w;
            ra[4] = v1.x; ra[5] = v1.y; ra[6] = v1.z; ra[7] = v1.w;
        }
    };
    auto stsA = [&](int j) {
        const uint32_t st = (uint32_t)(j % NST1) * STAGE1_B;
        __half2 p0 = __floats2half2_rn(ra[0], ra[1]);
        __half2 p1 = __floats2half2_rn(ra[2], ra[3]);
        __half2 p2 = __floats2half2_rn(ra[4], ra[5]);
        __half2 p3 = __floats2half2_rn(ra[6], ra[7]);
        uint4 v;
        v.x = *reinterpret_cast<uint32_t*>(&p0);
        v.y = *reinterpret_cast<uint32_t*>(&p1);
        v.z = *reinterpret_cast<uint32_t*>(&p2);
        v.w = *reinterpret_cast<uint32_t*>(&p3);
        *reinterpret_cast<uint4*>(smem + st + adst) = v;
    };

    float acc[2][4][4];
#pragma unroll
    for (int mt = 0; mt < 2; mt++)
#pragma unroll
        for (int nt = 0; nt < 4; nt++)
#pragma unroll
            for (int e = 0; e < 4; e++) acc[mt][nt][e] = 0.0f;

    // ldmatrix lane offsets (bytes within a tile)
    const int lr = lane & 7, lm = lane >> 3;
    const uint32_t offA = (uint32_t)(((lm & 1) * 8 + lr) * STRIDE + (lm >> 1) * 8) * 2;
    const uint32_t offB = (uint32_t)(((lm >> 1) * 8 + lr) * STRIDE + (lm & 1) * 8) * 2;
    const uint32_t rowA = (uint32_t)(wm * 32) * STRIDE * 2;
    const uint32_t rowB = (uint32_t)(wn * 32) * STRIDE * 2;

    loadA(0);
    produceB(0);
    produceB(1);
    produceB(2);

    for (int i = 0; i < nk; i++) {
        stsA(i);               // stage i%4 (A region); last consumed at iter i-4
        loadA(i + 1);
        CP_WAIT2();            // B group i landed
        __syncthreads();       // A STS visible; iter i-1 consumption done
        produceB(i + 3);       // stage (i-1)%4 — free now
        const uint32_t st = sb + (uint32_t)(i % NST1) * STAGE1_B;
        const uint32_t aB = st + rowA + offA;
        const uint32_t bB = st + A1_TILE_B + rowB + offB;
        // hoist ALL fragment loads (both k16 steps) ahead of the MMA burst
        uint32_t a0[8], b0[8], a1[8], b1[8];
        LDSM4(&a0[0], aB);
        LDSM4(&a0[4], aB + 16u * STRIDE * 2);
        LDSM4(&b0[0], bB);
        LDSM4(&b0[4], bB + 16u * STRIDE * 2);
        LDSM4(&a1[0], aB + 32);
        LDSM4(&a1[4], aB + 32 + 16u * STRIDE * 2);
        LDSM4(&b1[0], bB + 32);
        LDSM4(&b1[4], bB + 32 + 16u * STRIDE * 2);
#pragma unroll
        for (int mt = 0; mt < 2; mt++)
#pragma unroll
            for (int nt = 0; nt < 4; nt++)
                MMA_F16(acc[mt][nt], (&a0[mt * 4]), (&b0[nt * 2]));
#pragma unroll
        for (int mt = 0; mt < 2; mt++)
#pragma unroll
            for (int nt = 0; nt < 4; nt++)
                MMA_F16(acc[mt][nt], (&a1[mt * 4]), (&b1[nt * 2]));
    }

    // epilogue: store T as fp16
    const int er = lane >> 2, ec = (lane & 3) * 2;
#pragma unroll
    for (int nt = 0; nt < 4; nt++) {
        const int col = n0 + wn * 32 + nt * 8 + ec;
#pragma unroll
        for (int mt = 0; mt < 2; mt++) {
            const int r0g = m0 + wm * 32 + mt * 16 + er;
#pragma unroll
            for (int h = 0; h < 2; h++) {
                const int row = r0g + h * 8;
                __half2 o = __floats2half2_rn(acc[mt][nt][h * 2 + 0],
                                              acc[mt][nt][h * 2 + 1]);
                *reinterpret_cast<__half2*>(&T[(size_t)row * 256 + col]) = o;
            }
        }
    }
}

// ---------------- Stage 2: out = T @ U^T + bias ----------------
// BM=128, BN=128, 256 thr, warp tile 64x32 (2 wm x 4 wn, mt=4). NST=4, occ 2.
__global__ __launch_bounds__(256, 2)
void lr_gemm_s2(const __half* __restrict__ At, const __half* __restrict__ Bt,
                int K, int Nout, const float* __restrict__ bias,
                float* __restrict__ Cf) {
    extern __shared__ __align__(16) char smem[];
    const uint32_t sb = smem_u32(smem);

    const int tid  = threadIdx.x;
    const int lane = tid & 31;
    const int warp = tid >> 5;
    const int wm = warp & 1, wn = warp >> 1;
    const int m0 = blockIdx.y * 128;
    const int n0 = blockIdx.x * 128;
    const int nk = K / KT;    // 8

    // producers: row = tid>>1 (0..127), byte offset (tid&1)*32; 2 chunks per tile
    const int pr = tid >> 1, pb = (tid & 1) * 32;
    const __half* Ab = At + (size_t)(m0 + pr) * K + pb / 2;
    const __half* Bb = Bt + (size_t)(n0 + pr) * K + pb / 2;
    const uint32_t pdst = (uint32_t)(pr * STRIDE) * 2 + pb;

    auto produce = [&](int j) {
        if (j < nk) {
            const uint32_t st = sb + (uint32_t)(j % NST2) * STAGE2_B;
            const __half* as = Ab + (size_t)j * KT;
            const __half* bs = Bb + (size_t)j * KT;
            CP_ASYNC16(st + pdst,      as);
            CP_ASYNC16(st + pdst + 16, as + 8);
            CP_ASYNC16(st + A2_TILE_B + pdst,      bs);
            CP_ASYNC16(st + A2_TILE_B + pdst + 16, bs + 8);
        }
        CP_COMMIT();
    };

    float acc[4][4][4];
#pragma unroll
    for (int mt = 0; mt < 4; mt++)
#pragma unroll
        for (int nt = 0; nt < 4; nt++)
#pragma unroll
            for (int e = 0; e < 4; e++) acc[mt][nt][e] = 0.0f;

    const int lr = lane & 7, lm = lane >> 3;
    const uint32_t offA = (uint32_t)(((lm & 1) * 8 + lr) * STRIDE + (lm >> 1) * 8) * 2;
    const uint32_t offB = (uint32_t)(((lm >> 1) * 8 + lr) * STRIDE + (lm & 1) * 8) * 2;
    const uint32_t rowA = (uint32_t)(wm * 64) * STRIDE * 2;
    const uint32_t rowB = (uint32_t)(wn * 32) * STRIDE * 2;

    produce(0);
    produce(1);
    produce(2);

    for (int i = 0; i < nk; i++) {
        CP_WAIT2();
        __syncthreads();
        produce(i + 3);
        const uint32_t st = sb + (uint32_t)(i % NST2) * STAGE2_B;
        const uint32_t aB = st + rowA + offA;
        const uint32_t bB = st + A2_TILE_B + rowB + offB;
#pragma unroll
        for (int ks = 0; ks < 2; ks++) {
            const uint32_t kb = (uint32_t)ks * 16 * 2;
            uint32_t a[4][4], b[8];
#pragma unroll
            for (int mt = 0; mt < 4; mt++)
                LDSM4(a[mt], aB + kb + (uint32_t)mt * 16u * STRIDE * 2);
            LDSM4(&b[0], bB + kb);
            LDSM4(&b[4], bB + kb + 16u * STRIDE * 2);
#pragma unroll
            for (int mt = 0; mt < 4; mt++)
#pragma unroll
                for (int nt = 0; nt < 4; nt++)
                    MMA_F16(acc[mt][nt], a[mt], (&b[nt * 2]));
        }
    }

    const int er = lane >> 2, ec = (lane & 3) * 2;
#pragma unroll
    for (int nt = 0; nt < 4; nt++) {
        const int col = n0 + wn * 32 + nt * 8 + ec;
        const float b0 = bias[col], b1 = bias[col + 1];
#pragma unroll
        for (int mt = 0; mt < 4; mt++) {
            const int r0g = m0 + wm * 64 + mt * 16 + er;
#pragma unroll
            for (int h = 0; h < 2; h++) {
                const int row = r0g + h * 8;
                float2 o = make_float2(acc[mt][nt][h * 2 + 0] + b0,
                                       acc[mt][nt][h * 2 + 1] + b1);
                *reinterpret_cast<float2*>(&Cf[(size_t)row * Nout + col]) = o;
            }
        }
    }
}

// ---------------- launch ----------------
extern "C" void kernel_launch(void* const* d_in, const int* in_sizes, int n_in,
                              void* d_out, int out_size) {
    const float* x    = (const float*)d_in[0];   // [8192, 4096]
    const float* U    = (const float*)d_in[1];   // [4096, 256]
    const float* V    = (const float*)d_in[2];   // [256, 4096]
    const float* bias = (const float*)d_in[3];   // [4096]
    float* out = (float*)d_out;                  // [8192, 4096]

    __half *vt, *ut, *T;
    cudaGetSymbolAddress((void**)&vt, g_vt);
    cudaGetSymbolAddress((void**)&ut, g_ut);
    cudaGetSymbolAddress((void**)&T,  g_t);

    cudaFuncSetAttribute(lr_gemm_s1, cudaFuncAttributeMaxDynamicSharedMemorySize, SMEM1_SZ);
    cudaFuncSetAttribute(lr_gemm_s2, cudaFuncAttributeMaxDynamicSharedMemorySize, SMEM2_SZ);

    // convert V and U to fp16 (one tiny launch)
    const int n1 = 256 * 4096;
    cvt_vu<<<(2 * n1 / 4) / 256, 256>>>(V, vt, U, ut, n1);

    // Stage 1: T[8192,256] = x @ V^T (K=4096): 256 CTAs, occ 2
    lr_gemm_s1<<<dim3(256 / 128, 8192 / 64), 256, SMEM1_SZ>>>(x, vt, 4096, T);

    // Stage 2: out[8192,4096] = T @ U^T + bias (K=256): 2048 CTAs, occ 2
    lr_gemm_s2<<<dim3(4096 / 128, 8192 / 128), 256, SMEM2_SZ>>>(
        T, ut, 256, 4096, bias, out);
}